// round 3
// baseline (speedup 1.0000x reference)
#include <cuda_runtime.h>
#include <cuda_bf16.h>
#include <math.h>

#define BATCH 512
#define SEQ 256
#define EMBED 384
#define HEAD 64

// Scratch for projected Q, K, V (each 512*256*64 floats = 33.5 MB)
__device__ float g_Q[BATCH * SEQ * HEAD];
__device__ float g_K[BATCH * SEQ * HEAD];
__device__ float g_V[BATCH * SEQ * HEAD];

// ---------------------------------------------------------------------------
// tf32 helpers
// ---------------------------------------------------------------------------
__device__ __forceinline__ float f2tf_f(float x) {
    unsigned r;
    asm("cvt.rna.tf32.f32 %0, %1;" : "=r"(r) : "f"(x));
    return __uint_as_float(r);
}

__device__ __forceinline__ void mma_tf32(float* d, const unsigned* a,
                                         unsigned b0, unsigned b1) {
    asm volatile(
        "mma.sync.aligned.m16n8k8.row.col.f32.tf32.tf32.f32 "
        "{%0,%1,%2,%3}, {%4,%5,%6,%7}, {%8,%9}, {%0,%1,%2,%3};\n"
        : "+f"(d[0]), "+f"(d[1]), "+f"(d[2]), "+f"(d[3])
        : "r"(a[0]), "r"(a[1]), "r"(a[2]), "r"(a[3]), "r"(b0), "r"(b1));
}

// ---------------------------------------------------------------------------
// Kernel 1: fused projection as ONE tf32 GEMM.
// C[131072 x 192] = X[131072 x 384] @ [Wk | Wq | Wv] (384 x 192)
// Block: 256 thr (8 warps), tile M=128, N=192, k-chunk 32.
// Warp grid 4(m) x 2(n); warp tile 32 x 96 = 2 m-frags x 12 n-frags.
// All smem operands pre-converted to tf32 at staging time.
// ---------------------------------------------------------------------------
#define XPAD 36   // bank(row*36 + k) ≡ g*4 + t -> conflict-free frag loads
#define WPAD 200  // bank(k*200 + col) ≡ t*8 + g -> conflict-free frag loads

__global__ __launch_bounds__(256, 1)
void proj_kernel(const float* __restrict__ X,
                 const float* __restrict__ Wk,
                 const float* __restrict__ Wq,
                 const float* __restrict__ Wv)
{
    __shared__ float Xs[128][XPAD];   // 18.4 KB
    __shared__ float Ws[32][WPAD];    // 25.6 KB

    const int tid  = threadIdx.x;
    const int lane = tid & 31;
    const int warp = tid >> 5;
    const int g = lane >> 2;   // 0..7
    const int t = lane & 3;    // 0..3
    const int wm = warp & 3;   // rows wm*32 .. +31
    const int wn = warp >> 2;  // cols wn*96 .. +95
    const int r0 = blockIdx.x * 128;

    float acc[24][4];
#pragma unroll
    for (int f = 0; f < 24; f++)
#pragma unroll
        for (int j = 0; j < 4; j++) acc[f][j] = 0.f;

#pragma unroll 1
    for (int kk = 0; kk < EMBED; kk += 32) {
        // Stage X tile 128x32 (1024 float4, 4 per thread), cvt to tf32
#pragma unroll
        for (int i = 0; i < 4; i++) {
            int idx = tid + i * 256;
            int row = idx >> 3;
            int col = (idx & 7) * 4;
            float4 v = *(const float4*)(X + (size_t)(r0 + row) * EMBED + kk + col);
            v.x = f2tf_f(v.x); v.y = f2tf_f(v.y);
            v.z = f2tf_f(v.z); v.w = f2tf_f(v.w);
            *(float4*)&Xs[row][col] = v;
        }
        // Stage W tile 32x192 (concat K|Q|V; 1536 float4, 6 per thread), cvt
#pragma unroll
        for (int i = 0; i < 6; i++) {
            int idx = tid + i * 256;
            int row = idx / 48;
            int col = (idx % 48) * 4;
            const float* src;
            if (col < 64)       src = Wk + (size_t)(kk + row) * HEAD + col;
            else if (col < 128) src = Wq + (size_t)(kk + row) * HEAD + (col - 64);
            else                src = Wv + (size_t)(kk + row) * HEAD + (col - 128);
            float4 v = *(const float4*)src;
            v.x = f2tf_f(v.x); v.y = f2tf_f(v.y);
            v.z = f2tf_f(v.z); v.w = f2tf_f(v.w);
            *(float4*)&Ws[row][col] = v;
        }
        __syncthreads();

#pragma unroll
        for (int ks = 0; ks < 4; ks++) {
            const int kb = ks * 8;
            unsigned a0[4], a1[4];
            const int rA = wm * 32 + g;
            a0[0] = __float_as_uint(Xs[rA][kb + t]);
            a0[1] = __float_as_uint(Xs[rA + 8][kb + t]);
            a0[2] = __float_as_uint(Xs[rA][kb + t + 4]);
            a0[3] = __float_as_uint(Xs[rA + 8][kb + t + 4]);
            a1[0] = __float_as_uint(Xs[rA + 16][kb + t]);
            a1[1] = __float_as_uint(Xs[rA + 24][kb + t]);
            a1[2] = __float_as_uint(Xs[rA + 16][kb + t + 4]);
            a1[3] = __float_as_uint(Xs[rA + 24][kb + t + 4]);
#pragma unroll
            for (int f = 0; f < 12; f++) {
                int col = wn * 96 + f * 8 + g;
                unsigned b0 = __float_as_uint(Ws[kb + t][col]);
                unsigned b1 = __float_as_uint(Ws[kb + t + 4][col]);
                mma_tf32(acc[f], a0, b0, b1);
                mma_tf32(acc[12 + f], a1, b0, b1);
            }
        }
        __syncthreads();
    }

    // Epilogue: route columns to K / Q / V
#pragma unroll
    for (int mf = 0; mf < 2; mf++) {
#pragma unroll
        for (int f = 0; f < 12; f++) {
            const float* a = acc[mf * 12 + f];
            int n = wn * 96 + f * 8 + 2 * t;
            float* dst;
            int nn;
            if (n < 64)       { dst = g_K; nn = n; }
            else if (n < 128) { dst = g_Q; nn = n - 64; }
            else              { dst = g_V; nn = n - 128; }
            size_t row = (size_t)(r0 + wm * 32 + mf * 16 + g);
            *(float2*)&dst[row * HEAD + nn]       = make_float2(a[0], a[1]);
            *(float2*)&dst[(row + 8) * HEAD + nn] = make_float2(a[2], a[3]);
        }
    }
}

// ---------------------------------------------------------------------------
// Kernel 2: causal attention, tf32 tensor cores, flash-style online softmax.
// One block per batch (512 blocks, 256 thr = 8 warps).
// Each warp handles q-tiles {w, 15-w} (16 rows each) -> balanced causal work.
// K, V, Q, P all stored in smem already tf32-converted.
// ---------------------------------------------------------------------------
#define KVPAD 68
#define QPAD  68
#define PPAD  36

__global__ __launch_bounds__(256, 1)
void attn_kernel(float* __restrict__ out)
{
    extern __shared__ float sm[];
    float* Ks = sm;                       // [256][KVPAD]
    float* Vs = Ks + SEQ * KVPAD;         // [256][KVPAD]
    float* Qs = Vs + SEQ * KVPAD;         // [8][16][QPAD]
    float* Pb = Qs + 8 * 16 * QPAD;       // [8][16][PPAD]

    const int b    = blockIdx.x;
    const int tid  = threadIdx.x;
    const int lane = tid & 31;
    const int warp = tid >> 5;
    const int g = lane >> 2;
    const int t = lane & 3;
    const size_t base = (size_t)b * SEQ * HEAD;

    // Stage K, V for this batch, pre-converted to tf32 (coalesced float4)
    for (int i = tid; i < SEQ * HEAD / 4; i += 256) {
        int s = i >> 4;            // /16 float4 per row
        int d = (i & 15) * 4;
        float4 k4 = *(const float4*)&g_K[base + (size_t)s * HEAD + d];
        float4 v4 = *(const float4*)&g_V[base + (size_t)s * HEAD + d];
        k4.x = f2tf_f(k4.x); k4.y = f2tf_f(k4.y);
        k4.z = f2tf_f(k4.z); k4.w = f2tf_f(k4.w);
        v4.x = f2tf_f(v4.x); v4.y = f2tf_f(v4.y);
        v4.z = f2tf_f(v4.z); v4.w = f2tf_f(v4.w);
        *(float4*)&Ks[s * KVPAD + d] = k4;
        *(float4*)&Vs[s * KVPAD + d] = v4;
    }
    __syncthreads();

    float* Qw = Qs + warp * 16 * QPAD;
    float* Pw = Pb + warp * 16 * PPAD;

#pragma unroll
    for (int pass = 0; pass < 2; pass++) {
        const int qt = pass ? (15 - warp) : warp;
        const int qr0 = qt * 16;

        // Stage this warp's 16x64 Q tile, tf32-converted
#pragma unroll
        for (int i = 0; i < 8; i++) {
            int idx = lane + i * 32;
            int row = idx >> 4;
            int c4  = (idx & 15) * 4;
            float4 q4 = *(const float4*)&g_Q[base + (size_t)(qr0 + row) * HEAD + c4];
            q4.x = f2tf_f(q4.x); q4.y = f2tf_f(q4.y);
            q4.z = f2tf_f(q4.z); q4.w = f2tf_f(q4.w);
            *(float4*)&Qw[row * QPAD + c4] = q4;
        }
        __syncwarp();

        // Q fragments for 8 k-steps (head dim 64)
        unsigned qf[8][4];
#pragma unroll
        for (int ks = 0; ks < 8; ks++) {
            int kb = ks * 8;
            qf[ks][0] = __float_as_uint(Qw[g * QPAD + kb + t]);
            qf[ks][1] = __float_as_uint(Qw[(g + 8) * QPAD + kb + t]);
            qf[ks][2] = __float_as_uint(Qw[g * QPAD + kb + t + 4]);
            qf[ks][3] = __float_as_uint(Qw[(g + 8) * QPAD + kb + t + 4]);
        }

        float of[8][4];
#pragma unroll
        for (int f = 0; f < 8; f++)
#pragma unroll
            for (int j = 0; j < 4; j++) of[f][j] = 0.f;

        float m0 = -1e30f, m1 = -1e30f, l0 = 0.f, l1 = 0.f;
        const int rg  = qr0 + g;
        const int rg8 = rg + 8;
        const int jmax = (qr0 + 15) >> 5;

        for (int j = 0; j <= jmax; j++) {
            // ---- S = Q @ K^T for kv chunk [j*32, j*32+31] ----
            float s[4][4];
#pragma unroll
            for (int nf = 0; nf < 4; nf++)
#pragma unroll
                for (int e = 0; e < 4; e++) s[nf][e] = 0.f;

#pragma unroll
            for (int ks = 0; ks < 8; ks++) {
                int kb = ks * 8;
#pragma unroll
                for (int nf = 0; nf < 4; nf++) {
                    int col = j * 32 + nf * 8 + g;
                    unsigned b0 = __float_as_uint(Ks[col * KVPAD + kb + t]);
                    unsigned b1 = __float_as_uint(Ks[col * KVPAD + kb + t + 4]);
                    mma_tf32(s[nf], qf[ks], b0, b1);
                }
            }

            // scale + causal mask (only last kv tile crosses the diagonal)
#pragma unroll
            for (int nf = 0; nf < 4; nf++) {
                int c0 = j * 32 + nf * 8 + 2 * t;
                s[nf][0] *= 0.125f; s[nf][1] *= 0.125f;
                s[nf][2] *= 0.125f; s[nf][3] *= 0.125f;
                if (j == jmax) {
                    if (c0 > rg)      s[nf][0] = -1e30f;
                    if (c0 + 1 > rg)  s[nf][1] = -1e30f;
                    if (c0 > rg8)     s[nf][2] = -1e30f;
                    if (c0 + 1 > rg8) s[nf][3] = -1e30f;
                }
            }

            // ---- online softmax (rows g and g+8) ----
            float nm0 = m0, nm1 = m1;
#pragma unroll
            for (int nf = 0; nf < 4; nf++) {
                nm0 = fmaxf(nm0, fmaxf(s[nf][0], s[nf][1]));
                nm1 = fmaxf(nm1, fmaxf(s[nf][2], s[nf][3]));
            }
            nm0 = fmaxf(nm0, __shfl_xor_sync(0xFFFFFFFFu, nm0, 1));
            nm0 = fmaxf(nm0, __shfl_xor_sync(0xFFFFFFFFu, nm0, 2));
            nm1 = fmaxf(nm1, __shfl_xor_sync(0xFFFFFFFFu, nm1, 1));
            nm1 = fmaxf(nm1, __shfl_xor_sync(0xFFFFFFFFu, nm1, 2));

            float al0 = __expf(m0 - nm0);
            float al1 = __expf(m1 - nm1);

            float ps0 = 0.f, ps1 = 0.f;
#pragma unroll
            for (int nf = 0; nf < 4; nf++) {
                float p0 = __expf(s[nf][0] - nm0);
                float p1 = __expf(s[nf][1] - nm0);
                float p2 = __expf(s[nf][2] - nm1);
                float p3 = __expf(s[nf][3] - nm1);
                ps0 += p0 + p1;
                ps1 += p2 + p3;
                int cl = nf * 8 + 2 * t;
                *(float2*)&Pw[g * PPAD + cl] =
                    make_float2(f2tf_f(p0), f2tf_f(p1));
                *(float2*)&Pw[(g + 8) * PPAD + cl] =
                    make_float2(f2tf_f(p2), f2tf_f(p3));
            }
            ps0 += __shfl_xor_sync(0xFFFFFFFFu, ps0, 1);
            ps0 += __shfl_xor_sync(0xFFFFFFFFu, ps0, 2);
            ps1 += __shfl_xor_sync(0xFFFFFFFFu, ps1, 1);
            ps1 += __shfl_xor_sync(0xFFFFFFFFu, ps1, 2);

            l0 = l0 * al0 + ps0;
            l1 = l1 * al1 + ps1;
            m0 = nm0; m1 = nm1;

#pragma unroll
            for (int f = 0; f < 8; f++) {
                of[f][0] *= al0; of[f][1] *= al0;
                of[f][2] *= al1; of[f][3] *= al1;
            }
            __syncwarp();   // P writes visible to whole warp

            // ---- O += P @ V ----
#pragma unroll
            for (int ks = 0; ks < 4; ks++) {
                int kb = ks * 8;
                unsigned pa[4];
                pa[0] = __float_as_uint(Pw[g * PPAD + kb + t]);
                pa[1] = __float_as_uint(Pw[(g + 8) * PPAD + kb + t]);
                pa[2] = __float_as_uint(Pw[g * PPAD + kb + t + 4]);
                pa[3] = __float_as_uint(Pw[(g + 8) * PPAD + kb + t + 4]);
                int vr = j * 32 + kb;
#pragma unroll
                for (int nf = 0; nf < 8; nf++) {
                    int col = nf * 8 + g;
                    unsigned b0 = __float_as_uint(Vs[(vr + t) * KVPAD + col]);
                    unsigned b1 = __float_as_uint(Vs[(vr + t + 4) * KVPAD + col]);
                    mma_tf32(of[nf], pa, b0, b1);
                }
            }
            __syncwarp();   // done reading P before next tile overwrites
        }

        // Epilogue: normalize and store
        float inv0 = 1.f / l0;
        float inv1 = 1.f / l1;
#pragma unroll
        for (int nf = 0; nf < 8; nf++) {
            int col = nf * 8 + 2 * t;
            size_t row = (size_t)(qr0 + g);
            *(float2*)&out[base + row * HEAD + col] =
                make_float2(of[nf][0] * inv0, of[nf][1] * inv0);
            *(float2*)&out[base + (row + 8) * HEAD + col] =
                make_float2(of[nf][2] * inv1, of[nf][3] * inv1);
        }
    }
}

// ---------------------------------------------------------------------------
extern "C" void kernel_launch(void* const* d_in, const int* in_sizes, int n_in,
                              void* d_out, int out_size)
{
    const float* X  = (const float*)d_in[0];
    const float* Wk = (const float*)d_in[1];
    const float* Wq = (const float*)d_in[2];
    const float* Wv = (const float*)d_in[3];
    float* out = (float*)d_out;

    proj_kernel<<<(BATCH * SEQ) / 128, 256>>>(X, Wk, Wq, Wv);

    const int smem_bytes =
        (2 * SEQ * KVPAD + 8 * 16 * QPAD + 8 * 16 * PPAD) * (int)sizeof(float);
    static bool attr_set = false;
    if (!attr_set) {
        cudaFuncSetAttribute(attn_kernel,
                             cudaFuncAttributeMaxDynamicSharedMemorySize,
                             smem_bytes);
        attr_set = true;
    }
    attn_kernel<<<BATCH, 256, smem_bytes>>>(out);
}

// round 6
// speedup vs baseline: 1.4490x; 1.4490x over previous
#include <cuda_runtime.h>
#include <cuda_bf16.h>
#include <cstdint>
#include <math.h>

#define BATCH 512
#define SEQ 256
#define EMBED 384
#define HEAD 64

// Scratch for projected Q, K, V
__device__ float g_Q[BATCH * SEQ * HEAD];
__device__ float g_K[BATCH * SEQ * HEAD];
__device__ float g_V[BATCH * SEQ * HEAD];

// ---------------------------------------------------------------------------
// tf32 helpers
// ---------------------------------------------------------------------------
__device__ __forceinline__ float f2tf_f(float x) {
    unsigned r;
    asm("cvt.rna.tf32.f32 %0, %1;" : "=r"(r) : "f"(x));
    return __uint_as_float(r);
}

__device__ __forceinline__ void mma_tf32(float* d, const unsigned* a,
                                         unsigned b0, unsigned b1) {
    asm volatile(
        "mma.sync.aligned.m16n8k8.row.col.f32.tf32.tf32.f32 "
        "{%0,%1,%2,%3}, {%4,%5,%6,%7}, {%8,%9}, {%0,%1,%2,%3};\n"
        : "+f"(d[0]), "+f"(d[1]), "+f"(d[2]), "+f"(d[3])
        : "r"(a[0]), "r"(a[1]), "r"(a[2]), "r"(a[3]), "r"(b0), "r"(b1));
}

// ---------------------------------------------------------------------------
// Kernel 1: fused projection GEMM, software-pipelined, 512 threads.
// C[131072 x 192] = X[131072 x 384] @ [Wk|Wq|Wv]
// CTA tile M=128, N=192; k-chunks of 32, double-buffered smem.
// Warp grid 4(m) x 4(n); warp tile 32 x 48 = 2 m-frags x 6 n-frags.
// ---------------------------------------------------------------------------
#define XPAD 36    // bank(row*36 + k) = (4*row + k) % 32 -> frag loads hit 4g+t
#define WPAD 200   // bank(k*200 + col) = (8k + col) % 32 -> frag loads hit 8t+g
#define XS_FLOATS (128 * XPAD)     // 4608
#define WS_FLOATS (32 * WPAD)      // 6400
#define PROJ_SMEM ((2 * XS_FLOATS + 2 * WS_FLOATS) * 4)   // 88064 B

__global__ __launch_bounds__(512, 1)
void proj_kernel(const float* __restrict__ X,
                 const float* __restrict__ Wk,
                 const float* __restrict__ Wq,
                 const float* __restrict__ Wv)
{
    extern __shared__ float sm[];
    float* Xs[2] = {sm, sm + XS_FLOATS};
    float* Ws[2] = {sm + 2 * XS_FLOATS, sm + 2 * XS_FLOATS + WS_FLOATS};

    const int tid  = threadIdx.x;
    const int lane = tid & 31;
    const int warp = tid >> 5;
    const int g = lane >> 2;   // 0..7
    const int t = lane & 3;    // 0..3
    const int wm = warp & 3;   // m-warp: rows wm*32 .. +31
    const int wn = warp >> 2;  // n-warp: cols wn*48 .. +47
    const int r0 = blockIdx.x * 128;

    // precomputed staging indices
    const int xrow0 = tid >> 3;            // +0 / +64
    const int xc4   = (tid & 7) * 4;
    int wrow[3], wc[3];
    const float* wsrc[3];
#pragma unroll
    for (int j = 0; j < 3; j++) {
        int idx = tid + j * 512;
        wrow[j] = idx / 48;
        int c = (idx % 48) * 4;
        wc[j] = c;
        if (c < 64)       wsrc[j] = Wk + c;
        else if (c < 128) wsrc[j] = Wq + (c - 64);
        else              wsrc[j] = Wv + (c - 128);
    }

    float acc[12][4];
#pragma unroll
    for (int f = 0; f < 12; f++)
#pragma unroll
        for (int j = 0; j < 4; j++) acc[f][j] = 0.f;

    float4 xr[2], wr[3];

    // ---- prologue: load + store chunk 0 ----
#pragma unroll
    for (int j = 0; j < 2; j++)
        xr[j] = *(const float4*)(X + (size_t)(r0 + xrow0 + j * 64) * EMBED + xc4);
#pragma unroll
    for (int j = 0; j < 3; j++)
        wr[j] = *(const float4*)(wsrc[j] + (size_t)wrow[j] * HEAD);
#pragma unroll
    for (int j = 0; j < 2; j++) {
        float4 v = xr[j];
        v.x = f2tf_f(v.x); v.y = f2tf_f(v.y);
        v.z = f2tf_f(v.z); v.w = f2tf_f(v.w);
        *(float4*)&Xs[0][(xrow0 + j * 64) * XPAD + xc4] = v;
    }
#pragma unroll
    for (int j = 0; j < 3; j++) {
        float4 v = wr[j];
        v.x = f2tf_f(v.x); v.y = f2tf_f(v.y);
        v.z = f2tf_f(v.z); v.w = f2tf_f(v.w);
        *(float4*)&Ws[0][wrow[j] * WPAD + wc[j]] = v;
    }
    __syncthreads();

#pragma unroll 1
    for (int c = 0; c < 12; c++) {
        const int cb = c & 1;
        // issue global loads for next chunk (latency hidden by compute)
        if (c < 11) {
            const int kk = (c + 1) * 32;
#pragma unroll
            for (int j = 0; j < 2; j++)
                xr[j] = *(const float4*)(X + (size_t)(r0 + xrow0 + j * 64) * EMBED + kk + xc4);
#pragma unroll
            for (int j = 0; j < 3; j++)
                wr[j] = *(const float4*)(wsrc[j] + (size_t)(kk + wrow[j]) * HEAD);
        }

        // compute on current buffer
        const float* Xb = Xs[cb];
        const float* Wb = Ws[cb];
#pragma unroll
        for (int ks = 0; ks < 4; ks++) {
            const int kb = ks * 8;
            unsigned a0[4], a1[4];
            const int rA = wm * 32 + g;
            a0[0] = __float_as_uint(Xb[rA * XPAD + kb + t]);
            a0[1] = __float_as_uint(Xb[(rA + 8) * XPAD + kb + t]);
            a0[2] = __float_as_uint(Xb[rA * XPAD + kb + t + 4]);
            a0[3] = __float_as_uint(Xb[(rA + 8) * XPAD + kb + t + 4]);
            a1[0] = __float_as_uint(Xb[(rA + 16) * XPAD + kb + t]);
            a1[1] = __float_as_uint(Xb[(rA + 24) * XPAD + kb + t]);
            a1[2] = __float_as_uint(Xb[(rA + 16) * XPAD + kb + t + 4]);
            a1[3] = __float_as_uint(Xb[(rA + 24) * XPAD + kb + t + 4]);
#pragma unroll
            for (int f = 0; f < 6; f++) {
                int col = wn * 48 + f * 8 + g;
                unsigned b0 = __float_as_uint(Wb[(kb + t) * WPAD + col]);
                unsigned b1 = __float_as_uint(Wb[(kb + t + 4) * WPAD + col]);
                mma_tf32(acc[f], a0, b0, b1);
                mma_tf32(acc[6 + f], a1, b0, b1);
            }
        }

        // store next chunk into the other buffer (safe: nobody reads it now)
        if (c < 11) {
            const int nb = 1 - cb;
#pragma unroll
            for (int j = 0; j < 2; j++) {
                float4 v = xr[j];
                v.x = f2tf_f(v.x); v.y = f2tf_f(v.y);
                v.z = f2tf_f(v.z); v.w = f2tf_f(v.w);
                *(float4*)&Xs[nb][(xrow0 + j * 64) * XPAD + xc4] = v;
            }
#pragma unroll
            for (int j = 0; j < 3; j++) {
                float4 v = wr[j];
                v.x = f2tf_f(v.x); v.y = f2tf_f(v.y);
                v.z = f2tf_f(v.z); v.w = f2tf_f(v.w);
                *(float4*)&Ws[nb][wrow[j] * WPAD + wc[j]] = v;
            }
        }
        __syncthreads();
    }

    // ---- epilogue: route columns to K / Q / V ----
#pragma unroll
    for (int mf = 0; mf < 2; mf++) {
#pragma unroll
        for (int f = 0; f < 6; f++) {
            const float* a = acc[mf * 6 + f];
            int n = wn * 48 + f * 8 + 2 * t;
            float* dst;
            int nn;
            if (n < 64)       { dst = g_K; nn = n; }
            else if (n < 128) { dst = g_Q; nn = n - 64; }
            else              { dst = g_V; nn = n - 128; }
            size_t row = (size_t)(r0 + wm * 32 + mf * 16 + g);
            *(float2*)&dst[row * HEAD + nn]       = make_float2(a[0], a[1]);
            *(float2*)&dst[(row + 8) * HEAD + nn] = make_float2(a[2], a[3]);
        }
    }
}

// ---------------------------------------------------------------------------
// Kernel 2: causal attention, tf32 mma.sync, flash-style online softmax.
// (unchanged known-good 95.6us version)
// ---------------------------------------------------------------------------
#define KVPAD 68
#define QPAD  68
#define PPAD  36

__global__ __launch_bounds__(256, 1)
void attn_kernel(float* __restrict__ out)
{
    extern __shared__ float smf[];
    float* Ks = smf;
    float* Vs = Ks + SEQ * KVPAD;
    float* Qs = Vs + SEQ * KVPAD;
    float* Pb = Qs + 8 * 16 * QPAD;

    const int b    = blockIdx.x;
    const int tid  = threadIdx.x;
    const int lane = tid & 31;
    const int warp = tid >> 5;
    const int g = lane >> 2;
    const int t = lane & 3;
    const size_t base = (size_t)b * SEQ * HEAD;

    for (int i = tid; i < SEQ * HEAD / 4; i += 256) {
        int s = i >> 4;
        int d = (i & 15) * 4;
        float4 k4 = *(const float4*)&g_K[base + (size_t)s * HEAD + d];
        float4 v4 = *(const float4*)&g_V[base + (size_t)s * HEAD + d];
        k4.x = f2tf_f(k4.x); k4.y = f2tf_f(k4.y);
        k4.z = f2tf_f(k4.z); k4.w = f2tf_f(k4.w);
        v4.x = f2tf_f(v4.x); v4.y = f2tf_f(v4.y);
        v4.z = f2tf_f(v4.z); v4.w = f2tf_f(v4.w);
        *(float4*)&Ks[s * KVPAD + d] = k4;
        *(float4*)&Vs[s * KVPAD + d] = v4;
    }
    __syncthreads();

    float* Qw = Qs + warp * 16 * QPAD;
    float* Pw = Pb + warp * 16 * PPAD;

#pragma unroll
    for (int pass = 0; pass < 2; pass++) {
        const int qt = pass ? (15 - warp) : warp;
        const int qr0 = qt * 16;

#pragma unroll
        for (int i = 0; i < 8; i++) {
            int idx = lane + i * 32;
            int row = idx >> 4;
            int c4  = (idx & 15) * 4;
            float4 q4 = *(const float4*)&g_Q[base + (size_t)(qr0 + row) * HEAD + c4];
            q4.x = f2tf_f(q4.x); q4.y = f2tf_f(q4.y);
            q4.z = f2tf_f(q4.z); q4.w = f2tf_f(q4.w);
            *(float4*)&Qw[row * QPAD + c4] = q4;
        }
        __syncwarp();

        unsigned qf[8][4];
#pragma unroll
        for (int ks = 0; ks < 8; ks++) {
            int kb = ks * 8;
            qf[ks][0] = __float_as_uint(Qw[g * QPAD + kb + t]);
            qf[ks][1] = __float_as_uint(Qw[(g + 8) * QPAD + kb + t]);
            qf[ks][2] = __float_as_uint(Qw[g * QPAD + kb + t + 4]);
            qf[ks][3] = __float_as_uint(Qw[(g + 8) * QPAD + kb + t + 4]);
        }

        float of[8][4];
#pragma unroll
        for (int f = 0; f < 8; f++)
#pragma unroll
            for (int j = 0; j < 4; j++) of[f][j] = 0.f;

        float m0 = -1e30f, m1 = -1e30f, l0 = 0.f, l1 = 0.f;
        const int rg  = qr0 + g;
        const int rg8 = rg + 8;
        const int jmax = (qr0 + 15) >> 5;

        for (int j = 0; j <= jmax; j++) {
            float s[4][4];
#pragma unroll
            for (int nf = 0; nf < 4; nf++)
#pragma unroll
                for (int e = 0; e < 4; e++) s[nf][e] = 0.f;

#pragma unroll
            for (int ks = 0; ks < 8; ks++) {
                int kb = ks * 8;
#pragma unroll
                for (int nf = 0; nf < 4; nf++) {
                    int col = j * 32 + nf * 8 + g;
                    unsigned b0 = __float_as_uint(Ks[col * KVPAD + kb + t]);
                    unsigned b1 = __float_as_uint(Ks[col * KVPAD + kb + t + 4]);
                    mma_tf32(s[nf], qf[ks], b0, b1);
                }
            }

#pragma unroll
            for (int nf = 0; nf < 4; nf++) {
                int c0 = j * 32 + nf * 8 + 2 * t;
                s[nf][0] *= 0.125f; s[nf][1] *= 0.125f;
                s[nf][2] *= 0.125f; s[nf][3] *= 0.125f;
                if (j == jmax) {
                    if (c0 > rg)      s[nf][0] = -1e30f;
                    if (c0 + 1 > rg)  s[nf][1] = -1e30f;
                    if (c0 > rg8)     s[nf][2] = -1e30f;
                    if (c0 + 1 > rg8) s[nf][3] = -1e30f;
                }
            }

            float nm0 = m0, nm1 = m1;
#pragma unroll
            for (int nf = 0; nf < 4; nf++) {
                nm0 = fmaxf(nm0, fmaxf(s[nf][0], s[nf][1]));
                nm1 = fmaxf(nm1, fmaxf(s[nf][2], s[nf][3]));
            }
            nm0 = fmaxf(nm0, __shfl_xor_sync(0xFFFFFFFFu, nm0, 1));
            nm0 = fmaxf(nm0, __shfl_xor_sync(0xFFFFFFFFu, nm0, 2));
            nm1 = fmaxf(nm1, __shfl_xor_sync(0xFFFFFFFFu, nm1, 1));
            nm1 = fmaxf(nm1, __shfl_xor_sync(0xFFFFFFFFu, nm1, 2));

            float al0 = __expf(m0 - nm0);
            float al1 = __expf(m1 - nm1);

            float ps0 = 0.f, ps1 = 0.f;
#pragma unroll
            for (int nf = 0; nf < 4; nf++) {
                float p0 = __expf(s[nf][0] - nm0);
                float p1 = __expf(s[nf][1] - nm0);
                float p2 = __expf(s[nf][2] - nm1);
                float p3 = __expf(s[nf][3] - nm1);
                ps0 += p0 + p1;
                ps1 += p2 + p3;
                int cl = nf * 8 + 2 * t;
                *(float2*)&Pw[g * PPAD + cl] =
                    make_float2(f2tf_f(p0), f2tf_f(p1));
                *(float2*)&Pw[(g + 8) * PPAD + cl] =
                    make_float2(f2tf_f(p2), f2tf_f(p3));
            }
            ps0 += __shfl_xor_sync(0xFFFFFFFFu, ps0, 1);
            ps0 += __shfl_xor_sync(0xFFFFFFFFu, ps0, 2);
            ps1 += __shfl_xor_sync(0xFFFFFFFFu, ps1, 1);
            ps1 += __shfl_xor_sync(0xFFFFFFFFu, ps1, 2);

            l0 = l0 * al0 + ps0;
            l1 = l1 * al1 + ps1;
            m0 = nm0; m1 = nm1;

#pragma unroll
            for (int f = 0; f < 8; f++) {
                of[f][0] *= al0; of[f][1] *= al0;
                of[f][2] *= al1; of[f][3] *= al1;
            }
            __syncwarp();

#pragma unroll
            for (int ks = 0; ks < 4; ks++) {
                int kb = ks * 8;
                unsigned pa[4];
                pa[0] = __float_as_uint(Pw[g * PPAD + kb + t]);
                pa[1] = __float_as_uint(Pw[(g + 8) * PPAD + kb + t]);
                pa[2] = __float_as_uint(Pw[g * PPAD + kb + t + 4]);
                pa[3] = __float_as_uint(Pw[(g + 8) * PPAD + kb + t + 4]);
                int vr = j * 32 + kb;
#pragma unroll
                for (int nf = 0; nf < 8; nf++) {
                    int col = nf * 8 + g;
                    unsigned b0 = __float_as_uint(Vs[(vr + t) * KVPAD + col]);
                    unsigned b1 = __float_as_uint(Vs[(vr + t + 4) * KVPAD + col]);
                    mma_tf32(of[nf], pa, b0, b1);
                }
            }
            __syncwarp();
        }

        float inv0 = 1.f / l0;
        float inv1 = 1.f / l1;
#pragma unroll
        for (int nf = 0; nf < 8; nf++) {
            int col = nf * 8 + 2 * t;
            size_t row = (size_t)(qr0 + g);
            *(float2*)&out[base + row * HEAD + col] =
                make_float2(of[nf][0] * inv0, of[nf][1] * inv0);
            *(float2*)&out[base + (row + 8) * HEAD + col] =
                make_float2(of[nf][2] * inv1, of[nf][3] * inv1);
        }
    }
}

// ---------------------------------------------------------------------------
extern "C" void kernel_launch(void* const* d_in, const int* in_sizes, int n_in,
                              void* d_out, int out_size)
{
    const float* X  = (const float*)d_in[0];
    const float* Wk = (const float*)d_in[1];
    const float* Wq = (const float*)d_in[2];
    const float* Wv = (const float*)d_in[3];
    float* out = (float*)d_out;

    const int attn_smem =
        (2 * SEQ * KVPAD + 8 * 16 * QPAD + 8 * 16 * PPAD) * (int)sizeof(float);

    static bool attr_set = false;
    if (!attr_set) {
        cudaFuncSetAttribute(proj_kernel,
                             cudaFuncAttributeMaxDynamicSharedMemorySize,
                             PROJ_SMEM);
        cudaFuncSetAttribute(attn_kernel,
                             cudaFuncAttributeMaxDynamicSharedMemorySize,
                             attn_smem);
        attr_set = true;
    }

    proj_kernel<<<(BATCH * SEQ) / 128, 512, PROJ_SMEM>>>(X, Wk, Wq, Wv);
    attn_kernel<<<BATCH, 256, attn_smem>>>(out);
}